// round 13
// baseline (speedup 1.0000x reference)
#include <cuda_runtime.h>
#include <cuda_fp16.h>
#include <math.h>
#include <stdint.h>

#define T_TOK 4096
#define HDIM 1024
#define FDIM 512
#define NEXP 8
#define MAXP 4096

// ---------------- device scratch ----------------
__device__ int    g_cnt[NEXP];
__device__ int    g_tok[NEXP * MAXP];
__device__ float  g_wt [NEXP * MAXP];
__device__ int    g_pair[T_TOK * 2];
__device__ __half g_xh  [T_TOK * HDIM];
__device__ __half g_acth[T_TOK * 2 * FDIM];
__device__ float  g_dout[T_TOK * 2 * HDIM];

#define MMA16(c, a0, a1, a2, a3, b0, b1) \
    asm volatile("mma.sync.aligned.m16n8k16.row.col.f32.f16.f16.f32 " \
        "{%0,%1,%2,%3},{%4,%5,%6,%7},{%8,%9},{%0,%1,%2,%3};" \
        : "+f"((c)[0]), "+f"((c)[1]), "+f"((c)[2]), "+f"((c)[3]) \
        : "r"(a0), "r"(a1), "r"(a2), "r"(a3), "r"(b0), "r"(b1))

__device__ __forceinline__ uint32_t h2u(__half2 h) {
    uint32_t u; asm("mov.b32 %0, %1;" : "=r"(u) : "r"(*(uint32_t*)&h)); return u;
}

// smem (uint2 units): A 8q x 132m, B 8q x 132n, per buffer 2112 uint2 (R7 layout)
#define QST 132
#define BUF2 2112
#define AOFF(b) ((b) * BUF2)
#define BOFF(b) ((b) * BUF2 + 8 * QST)
#define META2 (2 * BUF2)
#define GEMM_SMEM (2 * BUF2 * 8 + 1024)

// map flat tile -> (expert, m0, gbase, cnt); tiles are 128 rows
__device__ __forceinline__ bool tile_map(int tile, int& e, int& m0, int& gbase, int& cnt) {
    int acc = 0, off = 0;
#pragma unroll
    for (int i = 0; i < NEXP; i++) {
        int c = g_cnt[i];
        int nt = (c + 127) >> 7;
        if (tile < acc + nt) { e = i; m0 = (tile - acc) << 7; gbase = off; cnt = c; return true; }
        acc += nt; off += c;
    }
    return false;
}

// ---------------- zero counters ----------------
__global__ void zero_cnt_kernel() { if (threadIdx.x < NEXP) g_cnt[threadIdx.x] = 0; }

// ---------------- router v2: smem-cached Wr (expert-major), 32 tokens/block ----------------
__global__ __launch_bounds__(256) void router_kernel(
    const float* __restrict__ x, const float* __restrict__ Wr)
{
    __shared__ float s_wrT[NEXP * HDIM];   // 32KB
    int tid = threadIdx.x;
#pragma unroll
    for (int j = 0; j < 8; j++) {
        int idx = (j * 256 + tid) * 4;
        float4 v = *(const float4*)(Wr + idx);
        s_wrT[((idx + 0) & 7) * HDIM + ((idx + 0) >> 3)] = v.x;
        s_wrT[((idx + 1) & 7) * HDIM + ((idx + 1) >> 3)] = v.y;
        s_wrT[((idx + 2) & 7) * HDIM + ((idx + 2) >> 3)] = v.z;
        s_wrT[((idx + 3) & 7) * HDIM + ((idx + 3) >> 3)] = v.w;
    }
    __syncthreads();

    int lane = tid & 31, wid = tid >> 5;
    for (int tt = 0; tt < 4; tt++) {
        int t = blockIdx.x * 32 + wid * 4 + tt;
        const float* xr = x + (size_t)t * HDIM;
        float acc[NEXP];
#pragma unroll
        for (int e = 0; e < NEXP; e++) acc[e] = 0.0f;
        for (int h = lane; h < HDIM; h += 32) {
            float xv = xr[h];
            g_xh[(size_t)t * HDIM + h] = __float2half_rn(xv);
#pragma unroll
            for (int e = 0; e < NEXP; e++)
                acc[e] = fmaf(xv, s_wrT[e * HDIM + h], acc[e]);
        }
#pragma unroll
        for (int e = 0; e < NEXP; e++)
#pragma unroll
            for (int o = 16; o > 0; o >>= 1)
                acc[e] += __shfl_xor_sync(0xFFFFFFFFu, acc[e], o);
        if (lane == 0) {
            float m = acc[0];
#pragma unroll
            for (int e = 1; e < NEXP; e++) m = fmaxf(m, acc[e]);
            float p[NEXP];
#pragma unroll
            for (int e = 0; e < NEXP; e++) p[e] = expf(acc[e] - m);
            int i0 = 0;
#pragma unroll
            for (int e = 1; e < NEXP; e++) if (p[e] > p[i0]) i0 = e;
            int i1 = (i0 == 0) ? 1 : 0;
#pragma unroll
            for (int e = 0; e < NEXP; e++) if (e != i0 && p[e] > p[i1]) i1 = e;
            float s = p[i0] + p[i1];
            int p0 = atomicAdd(&g_cnt[i0], 1);
            g_tok[i0 * MAXP + p0] = t; g_wt[i0 * MAXP + p0] = p[i0] / s;
            g_pair[t * 2 + 0] = (i0 << 12) | p0;
            int p1 = atomicAdd(&g_cnt[i1], 1);
            g_tok[i1 * MAXP + p1] = t; g_wt[i1 * MAXP + p1] = p[i1] / s;
            g_pair[t * 2 + 1] = (i1 << 12) | p1;
        }
    }
}

// =====================================================================
// gate+up fp16 GEMM + SwiGLU (R7 core). Block 128m x 128n', BK=32,
// 256 threads, 8 warps (2m x 4n), warp 64x32, 2 CTAs/SM.
// =====================================================================
__global__ __launch_bounds__(256, 2) void mg_gateup(
    const float* __restrict__ Wg,
    const float* __restrict__ Wu)
{
    extern __shared__ uint2 sm2[];
    int e, m0, gbase, cnt;
    if (!tile_map(blockIdx.x, e, m0, gbase, cnt)) return;
    int f0 = blockIdx.y * 64;

    int tid = threadIdx.x, lane = tid & 31, wid = tid >> 5;
    int wmi = wid >> 2, wni = wid & 3;
    int lr = lane >> 2, l3 = lane & 3;

    int*   stok = (int*)(sm2 + META2);
    float* swt  = (float*)(sm2 + META2 + 64);
    if (tid < 128) {
        int r = m0 + tid, rc = min(r, cnt - 1);
        stok[tid] = g_tok[e * MAXP + rc];
        swt[tid]  = (r < cnt) ? g_wt[e * MAXP + rc] : 0.0f;
    }
    __syncthreads();

    int am = tid >> 1, kh = (tid & 1) * 16;
    const __half* arow = g_xh + (size_t)stok[am] * HDIM + kh;
    int aqb = (tid & 1) * 4;
    int bp = (wid & 3) + 8 * (wid >> 2);
    int n4 = lane * 4;
    int bmat = (n4 >> 4) & 1;
    int bf = ((n4 >> 5) << 4) + (((n4 >> 3) & 1) << 3) + (n4 & 7);
    const float* wsel = (bmat ? Wu : Wg) + (size_t)e * HDIM * FDIM + f0 + bf;

    uint4 au0, au1;
    float4 bv0, bv1, bv2, bv3;
    auto LOADG = [&](int s) {
        int kb = s * 32;
        const uint4* ap = (const uint4*)(arow + kb);
        au0 = ap[0]; au1 = ap[1];
        const float* bp0 = wsel + (size_t)(kb + 2 * bp) * FDIM;
        bv0 = *(const float4*)bp0;
        bv1 = *(const float4*)(bp0 + FDIM);
        bv2 = *(const float4*)(bp0 + 8 * FDIM);
        bv3 = *(const float4*)(bp0 + 9 * FDIM);
    };
    auto STORES = [&](int b) {
        uint2* A = sm2 + AOFF(b);
        uint2* B = sm2 + BOFF(b);
        const uint32_t* a0 = (const uint32_t*)&au0;
        const uint32_t* a1 = (const uint32_t*)&au1;
#pragma unroll
        for (int j = 0; j < 4; j++)
            A[(aqb + j) * QST + am] = make_uint2(a0[j], a1[j]);
        const float* v0 = (const float*)&bv0;
        const float* v1 = (const float*)&bv1;
        const float* v2 = (const float*)&bv2;
        const float* v3 = (const float*)&bv3;
#pragma unroll
        for (int j = 0; j < 4; j++) {
            uint32_t lo = h2u(__floats2half2_rn(v0[j], v1[j]));
            uint32_t hi = h2u(__floats2half2_rn(v2[j], v3[j]));
            B[wid * QST + n4 + j] = make_uint2(lo, hi);
        }
    };

    float c[4][4][4];
#pragma unroll
    for (int a = 0; a < 4; a++)
#pragma unroll
        for (int b = 0; b < 4; b++)
#pragma unroll
            for (int k = 0; k < 4; k++) c[a][b][k] = 0.0f;

    LOADG(0); STORES(0);
    const int NS = HDIM / 32;
    for (int s = 0; s < NS; s++) {
        __syncthreads();
        if (s + 1 < NS) LOADG(s + 1);
        uint2* A = sm2 + AOFF(s & 1);
        uint2* B = sm2 + BOFF(s & 1);
#pragma unroll
        for (int kk = 0; kk < 2; kk++) {
            int q = kk * 4 + l3;
            uint2 af[4], ah[4];
#pragma unroll
            for (int mt = 0; mt < 4; mt++) {
                int m = wmi * 64 + mt * 16 + lr;
                af[mt] = A[q * QST + m];
                ah[mt] = A[q * QST + m + 8];
            }
#pragma unroll
            for (int nt = 0; nt < 4; nt++) {
                uint2 b = B[q * QST + wni * 32 + nt * 8 + lr];
#pragma unroll
                for (int mt = 0; mt < 4; mt++)
                    MMA16(c[mt][nt], af[mt].x, ah[mt].x, af[mt].y, ah[mt].y, b.x, b.y);
            }
        }
        if (s + 1 < NS) STORES((s + 1) & 1);
    }

    // epilogue: nt 0,1 gate / nt 2,3 up
#pragma unroll
    for (int mt = 0; mt < 4; mt++)
#pragma unroll
        for (int rr = 0; rr < 2; rr++) {
            int row = wmi * 64 + mt * 16 + lr + rr * 8;
            if (m0 + row < cnt) {
                float w = swt[row];
                __half* dst = g_acth + (size_t)(gbase + m0 + row) * FDIM + f0 + wni * 16 + 2 * l3;
#pragma unroll
                for (int ntl = 0; ntl < 2; ntl++) {
                    float gv0 = c[mt][ntl][rr * 2],     gv1 = c[mt][ntl][rr * 2 + 1];
                    float uv0 = c[mt][ntl + 2][rr * 2], uv1 = c[mt][ntl + 2][rr * 2 + 1];
                    float o0 = w * (gv0 / (1.0f + expf(-gv0))) * uv0;
                    float o1 = w * (gv1 / (1.0f + expf(-gv1))) * uv1;
                    *(__half2*)(dst + ntl * 8) = __floats2half2_rn(o0, o1);
                }
            }
        }
}

// =====================================================================
// down fp16 GEMM (R7 core). Block 128m x 128h, BK=32, warp 64x32.
// =====================================================================
__global__ __launch_bounds__(256, 2) void mg_down(const float* __restrict__ Wd)
{
    extern __shared__ uint2 sm2[];
    int e, m0, gbase, cnt;
    if (!tile_map(blockIdx.x, e, m0, gbase, cnt)) return;
    int h0 = blockIdx.y * 128;

    int tid = threadIdx.x, lane = tid & 31, wid = tid >> 5;
    int wmi = wid >> 2, wni = wid & 3;
    int lr = lane >> 2, l3 = lane & 3;

    int am = tid >> 1, kh = (tid & 1) * 16;
    const __half* arow = g_acth + (size_t)(gbase + min(m0 + am, cnt - 1)) * FDIM + kh;
    int aqb = (tid & 1) * 4;
    int bp = (wid & 3) + 8 * (wid >> 2);
    int n4 = lane * 4;
    const float* wsel = Wd + (size_t)e * FDIM * HDIM + h0 + n4;

    uint4 au0, au1;
    float4 bv0, bv1, bv2, bv3;
    auto LOADG = [&](int s) {
        int kb = s * 32;
        const uint4* ap = (const uint4*)(arow + kb);
        au0 = ap[0]; au1 = ap[1];
        const float* bp0 = wsel + (size_t)(kb + 2 * bp) * HDIM;
        bv0 = *(const float4*)bp0;
        bv1 = *(const float4*)(bp0 + HDIM);
        bv2 = *(const float4*)(bp0 + 8 * HDIM);
        bv3 = *(const float4*)(bp0 + 9 * HDIM);
    };
    auto STORES = [&](int b) {
        uint2* A = sm2 + AOFF(b);
        uint2* B = sm2 + BOFF(b);
        const uint32_t* a0 = (const uint32_t*)&au0;
        const uint32_t* a1 = (const uint32_t*)&au1;
#pragma unroll
        for (int j = 0; j < 4; j++)
            A[(aqb + j) * QST + am] = make_uint2(a0[j], a1[j]);
        const float* v0 = (const float*)&bv0;
        const float* v1 = (const float*)&bv1;
        const float* v2 = (const float*)&bv2;
        const float* v3 = (const float*)&bv3;
#pragma unroll
        for (int j = 0; j < 4; j++) {
            uint32_t lo = h2u(__floats2half2_rn(v0[j], v1[j]));
            uint32_t hi = h2u(__floats2half2_rn(v2[j], v3[j]));
            B[wid * QST + n4 + j] = make_uint2(lo, hi);
        }
    };

    float c[4][4][4];
#pragma unroll
    for (int a = 0; a < 4; a++)
#pragma unroll
        for (int b = 0; b < 4; b++)
#pragma unroll
            for (int k = 0; k < 4; k++) c[a][b][k] = 0.0f;

    LOADG(0); STORES(0);
    const int NS = FDIM / 32;
    for (int s = 0; s < NS; s++) {
        __syncthreads();
        if (s + 1 < NS) LOADG(s + 1);
        uint2* A = sm2 + AOFF(s & 1);
        uint2* B = sm2 + BOFF(s & 1);
#pragma unroll
        for (int kk = 0; kk < 2; kk++) {
            int q = kk * 4 + l3;
            uint2 af[4], ah[4];
#pragma unroll
            for (int mt = 0; mt < 4; mt++) {
                int m = wmi * 64 + mt * 16 + lr;
                af[mt] = A[q * QST + m];
                ah[mt] = A[q * QST + m + 8];
            }
#pragma unroll
            for (int nt = 0; nt < 4; nt++) {
                uint2 b = B[q * QST + wni * 32 + nt * 8 + lr];
#pragma unroll
                for (int mt = 0; mt < 4; mt++)
                    MMA16(c[mt][nt], af[mt].x, ah[mt].x, af[mt].y, ah[mt].y, b.x, b.y);
            }
        }
        if (s + 1 < NS) STORES((s + 1) & 1);
    }

#pragma unroll
    for (int mt = 0; mt < 4; mt++)
#pragma unroll
        for (int rr = 0; rr < 2; rr++) {
            int row = wmi * 64 + mt * 16 + lr + rr * 8;
            if (m0 + row < cnt) {
                float* dst = g_dout + (size_t)(gbase + m0 + row) * HDIM + h0 + wni * 32 + 2 * l3;
#pragma unroll
                for (int nt = 0; nt < 4; nt++)
                    *(float2*)(dst + nt * 8) =
                        make_float2(c[mt][nt][rr * 2], c[mt][nt][rr * 2 + 1]);
            }
        }
}

// ---------------- combine (fp32, inline offsets) ----------------
__global__ __launch_bounds__(256) void combine_kernel(float* __restrict__ out)
{
    int idx = blockIdx.x * blockDim.x + threadIdx.x;
    int t = idx >> 8;
    int hq = (idx & 255) * 4;
    int v0 = g_pair[t * 2 + 0], v1 = g_pair[t * 2 + 1];
    int e0 = v0 >> 12, e1 = v1 >> 12;
    int off0 = 0, off1 = 0;
#pragma unroll
    for (int i = 0; i < NEXP; i++) {
        int ci = g_cnt[i];
        if (i < e0) off0 += ci;
        if (i < e1) off1 += ci;
    }
    int gi0 = off0 + (v0 & (MAXP - 1));
    int gi1 = off1 + (v1 & (MAXP - 1));
    float4 a = *(const float4*)(g_dout + (size_t)gi0 * HDIM + hq);
    float4 b = *(const float4*)(g_dout + (size_t)gi1 * HDIM + hq);
    float4 o = {a.x + b.x, a.y + b.y, a.z + b.z, a.w + b.w};
    *(float4*)(out + (size_t)t * HDIM + hq) = o;
}

// ---------------- launch ----------------
extern "C" void kernel_launch(void* const* d_in, const int* in_sizes, int n_in,
                              void* d_out, int out_size)
{
    const float* x  = (const float*)d_in[0];
    const float* Wr = (const float*)d_in[1];
    const float* Wg = (const float*)d_in[2];
    const float* Wu = (const float*)d_in[3];
    const float* Wd = (const float*)d_in[4];
    float* out = (float*)d_out;

    cudaFuncSetAttribute(mg_gateup, cudaFuncAttributeMaxDynamicSharedMemorySize, GEMM_SMEM);
    cudaFuncSetAttribute(mg_down,   cudaFuncAttributeMaxDynamicSharedMemorySize, GEMM_SMEM);

    zero_cnt_kernel<<<1, 32>>>();
    router_kernel<<<T_TOK / 32, 256>>>(x, Wr);

    dim3 gg(72, FDIM / 64);
    mg_gateup<<<gg, 256, GEMM_SMEM>>>(Wg, Wu);

    dim3 gd(72, HDIM / 128);
    mg_down<<<gd, 256, GEMM_SMEM>>>(Wd);

    combine_kernel<<<(T_TOK * HDIM / 4) / 256, 256>>>(out);
}